// round 3
// baseline (speedup 1.0000x reference)
#include <cuda_runtime.h>
#include <cstdint>
#include <cstddef>

#define TPB 32          // threads per block = one warp; 1 thread = 1 batch
#define MPROP 36        // proposals per batch
#define NS 10           // top-k kept

// Fused piecewise-linear eval: tab[i] = (cs[min(i,16)], nw[min(i+1,16)])
// pwl(x) = cs[min(ip,16)] + frac * nw[min(ip+1,16)],  ip = floor(16x), frac unclamped.
__device__ __forceinline__ float pwl_eval(const float2* __restrict__ t, float x) {
    float xd = x * 16.0f;
    int ip = (int)xd;                 // x >= 0 in all call sites -> trunc == floor
    float frac = xd - (float)ip;
    int i = min(ip, 16);
    float2 e = t[i];
    return __fmaf_rn(frac, e.y, e.x);
}

__global__ __launch_bounds__(TPB)
void count_kernel(const float* __restrict__ boxes,      // [B,4,36]
                  const float* __restrict__ attention,  // [B,36]
                  const float* __restrict__ fw,         // [8,17]
                  float* __restrict__ out,              // [B,11]
                  int B)
{
    __shared__ float2 s_tab[8][18];          // fused (cs, nw) tables
    __shared__ float  s_att[TPB][MPROP + 1]; // pad 37 -> conflict-free column scans

    const int tid = threadIdx.x;

    // ---- build PWL tables (8 threads, one function each) ----
    if (tid < 8) {
        float aw[17];
        float s = 0.0f;
        #pragma unroll
        for (int k = 0; k < 17; k++) { aw[k] = fabsf(fw[tid * 17 + k]); s += aw[k]; }
        float nw[17], cs[17];
        #pragma unroll
        for (int k = 0; k < 17; k++) nw[k] = aw[k] / s;
        cs[0] = nw[0];
        #pragma unroll
        for (int k = 1; k < 17; k++) cs[k] = cs[k - 1] + nw[k];
        #pragma unroll
        for (int i = 0; i < 18; i++)
            s_tab[tid][i] = make_float2(cs[min(i, 16)], nw[min(i + 1, 16)]);
    }

    const int b = blockIdx.x * TPB + tid;
    const bool active = (b < B);

    // ---- stream this thread's attention row into shared ----
    if (active) {
        const float4* ap = (const float4*)(attention + (size_t)b * MPROP);
        #pragma unroll
        for (int k = 0; k < MPROP / 4; k++) {
            float4 v = ap[k];
            s_att[tid][4 * k + 0] = v.x;
            s_att[tid][4 * k + 1] = v.y;
            s_att[tid][4 * k + 2] = v.z;
            s_att[tid][4 * k + 3] = v.w;
        }
    }
    __syncthreads();   // tables visible (uniform barrier)

    if (!active) return;

    // ---- top-10 of 36: 10 rounds of register max-tree + smem knockout ----
    float sat[NS];
    int   six[NS];
    #pragma unroll 1
    for (int r = 0; r < NS; r++) {
        float wv[MPROP];
        int   wi[MPROP];
        #pragma unroll
        for (int j = 0; j < MPROP; j++) { wv[j] = s_att[tid][j]; wi[j] = j; }
        // left-biased merges (ties keep lower slot) -- order-invariant downstream
        #define MRG(a_, b_) { if (wv[b_] > wv[a_]) { wv[a_] = wv[b_]; wi[a_] = wi[b_]; } }
        #pragma unroll
        for (int k = 0; k < 18; k++) MRG(k, k + 18)   // 36 -> 18
        #pragma unroll
        for (int k = 0; k < 9; k++)  MRG(k, k + 9)    // 18 -> 9
        #pragma unroll
        for (int k = 0; k < 4; k++)  MRG(k, k + 5)    // 9 -> 5
        #pragma unroll
        for (int k = 0; k < 2; k++)  MRG(k, k + 3)    // 5 -> 3
        MRG(0, 2)                                     // 3 -> 2
        MRG(0, 1)                                     // 2 -> 1
        #undef MRG
        sat[r] = wv[0];
        six[r] = wi[0];
        s_att[tid][wi[0]] = __int_as_float(0xff800000);  // knock out winner (-inf)
    }

    // ---- gather boxes for selected, areas, sigmoid(att) ----
    const float* bb = boxes + (size_t)b * (4 * MPROP);
    float y1[NS], x1[NS], y2[NS], x2[NS], ar[NS], as_[NS];
    #pragma unroll
    for (int r = 0; r < NS; r++) {
        int ii = six[r];
        y1[r] = bb[ii];
        x1[r] = bb[MPROP + ii];
        y2[r] = bb[2 * MPROP + ii];
        x2[r] = bb[3 * MPROP + ii];
        ar[r] = fmaxf(y2[r] - y1[r], 0.0f) * fmaxf(x2[r] - x1[r], 0.0f);
        as_[r] = __fdividef(1.0f, 1.0f + __expf(-sat[r]));
    }

    const float2* t0 = s_tab[0];
    const float2* t1 = s_tab[1];
    const float2* t2 = s_tab[2];
    const float2* t5 = s_tab[5];
    const float2* t6 = s_tab[6];
    const float2* t7 = s_tab[7];

    // ---- pass 1: similarity row sums  (sim = f2(1-|da|) * C, C = f2(1)^10) ----
    const float f2one = s_tab[2][16].x;     // pwl2(1.0) = cs2[16]
    float srow[NS];
    #pragma unroll
    for (int i = 0; i < NS; i++) srow[i] = f2one;   // diagonal term f2(1-0)
    #pragma unroll
    for (int i = 0; i < NS; i++) {
        #pragma unroll
        for (int j = i + 1; j < NS; j++) {
            float v = pwl_eval(t2, 1.0f - fabsf(as_[i] - as_[j]));
            srow[i] += v;
            srow[j] += v;
        }
    }
    float C2 = f2one * f2one, C4 = C2 * C2, C8 = C4 * C4;
    float C = C8 * C2;                       // f2(1)^10
    float rr[NS];
    #pragma unroll
    for (int i = 0; i < NS; i++) rr[i] = __fdividef(1.0f, C * srow[i]);  // 1/s_i

    // ---- pass 2: off-diagonal pairs (symmetric, x2 at the end) ----
    float scoreO = 0.0f, pdO = 0.0f;
    #pragma unroll
    for (int i = 0; i < NS; i++) {
        #pragma unroll
        for (int j = i + 1; j < NS; j++) {
            float ty  = fmaxf(y1[i], y1[j]);
            float tx  = fmaxf(x1[i], x1[j]);
            float by  = fminf(y2[i], y2[j]);
            float bx  = fminf(x2[i], x2[j]);
            float inter = fmaxf(by - ty, 0.0f) * fmaxf(bx - tx, 0.0f);
            float uni   = ar[i] + ar[j] - inter + 1e-12f;
            float dm    = fmaxf(1.0f - __fdividef(inter, uni), 0.0f);
            float Aij   = as_[i] * as_[j];
            float f0v = pwl_eval(t0, Aij);
            float f1v = pwl_eval(t1, dm);
            float f6v = pwl_eval(t6, dm);
            scoreO = __fmaf_rn(f0v * f1v, rr[i] * rr[j], scoreO);
            pdO += fabsf(f6v - 0.5f);                 // p_d = |f6(Dm) - 0.5|
        }
    }

    // ---- diagonal terms + corr + p_a ----
    float scoreD = 0.0f, corrS = 0.0f, pdD = 0.0f, paS = 0.0f;
    #pragma unroll
    for (int r = 0; r < NS; r++) {
        // iou(box,box) = area/(area+1e-12)  (== 0 for degenerate boxes -> Dm_ii = 1)
        float dmd = 1.0f - __fdividef(ar[r], ar[r] + 1e-12f);
        float a2  = as_[r] * as_[r];
        float f0v = pwl_eval(t0, a2);
        float f1v = pwl_eval(t1, dmd);
        scoreD = __fmaf_rn(f0v * f1v, rr[r] * rr[r], scoreD);
        corrS  = __fmaf_rn(f0v, rr[r], corrS);
        pdD   += fabsf(pwl_eval(t6, dmd) - 0.5f);     // p_d = |f6(Dm) - 0.5|
        paS   += fabsf(pwl_eval(t5, as_[r]) - 0.5f);
    }

    float score_sum = 2.0f * scoreO + scoreD;
    float pd_mean   = (2.0f * pdO + pdD) * 0.01f;  // mean over 10x10
    float pa_mean   = paS * 0.1f;
    float gate = pwl_eval(t7, pa_mean + pd_mean);

    float modE = score_sum + corrS;
    float c  = sqrtf(modE + 1e-20f);
    float cc = fminf(c, 10.0f);                    // c >= 0 already
    int   ipc  = (int)cc;
    float fr   = cc - (float)ipc;
    int   i0 = min(ipc, NS);
    int   i1 = min(ipc + 1, NS);

    float* ob = out + (size_t)b * (NS + 1);
    #pragma unroll
    for (int k = 0; k <= NS; k++) {
        float v = ((k == i0) ? (1.0f - fr) : 0.0f) + ((k == i1) ? fr : 0.0f);
        ob[k] = gate * v;
    }
}

extern "C" void kernel_launch(void* const* d_in, const int* in_sizes, int n_in,
                              void* d_out, int out_size) {
    const float* boxes     = (const float*)d_in[0];
    const float* attention = (const float*)d_in[1];
    const float* fw        = (const float*)d_in[2];
    float* out             = (float*)d_out;
    (void)n_in; (void)out_size;
    int B = in_sizes[1] / MPROP;
    int grid = (B + TPB - 1) / TPB;
    count_kernel<<<grid, TPB>>>(boxes, attention, fw, out, B);
}